// round 16
// baseline (speedup 1.0000x reference)
#include <cuda_runtime.h>
#include <cuda_bf16.h>

// NMU forward: y[b,o] = prod_d ( M_hat[d,o]*x[b,d] + (1 - M_hat[d,o]) )
//            = prod_d ( M_hat[d,o]*(x[b,d]-1) + 1 )
// B=16384, D=256, O=32, fp32.
//
// R16 = R5 verbatim — the empirically fastest kernel (15.616us kernel,
// 16.864us bench) across 15 rounds of structural search.
//
// Roofline closure (R5..R15 evidence):
//  - algebraic floor: 2 fp32 ops/term (1 combine of u with its private m +
//    1 fold into the product; pair/quad expansions and divide-through forms
//    all return >= 2 ops/term) -> 268M lane-ops total.
//  - hardware floor: fp32 pipe sustains 64 lanes/cyc/SM (packed f32x2 is
//    rt-4 effective, scalar rt-2 — identical throughput; invariant across
//    occupancy 44-66%, LDS 47-64%, op mix, pipelining) -> 28.3K cyc ~ 15.4us.
//  - this kernel measures 15.6us = 99% of that floor.
//
// Structure: warp owns 32 d's with 16 packed m-pairs in registers; u = x-1
// staged d-major in smem (float4 in/out); hot loop per row: 8 broadcast
// LDS.128 + 16 fma2 + 15 mul2 in 2 chains; 8-wide partial combine via smem.

#define NMU_D   256
#define NMU_O   32
#define NMU_R   8         // rows per block
#define NMU_NW  8         // warps per block
#define NMU_DPW 32        // d's per warp

__device__ __forceinline__ unsigned long long f2_fma(unsigned long long a,
                                                     unsigned long long b,
                                                     unsigned long long c) {
    unsigned long long d;
    asm("fma.rn.f32x2 %0, %1, %2, %3;" : "=l"(d) : "l"(a), "l"(b), "l"(c));
    return d;
}
__device__ __forceinline__ unsigned long long f2_mul(unsigned long long a,
                                                     unsigned long long b) {
    unsigned long long d;
    asm("mul.rn.f32x2 %0, %1, %2;" : "=l"(d) : "l"(a), "l"(b));
    return d;
}
__device__ __forceinline__ unsigned long long pack2(float a, float b) {
    return ((unsigned long long)__float_as_uint(b) << 32) |
           (unsigned long long)__float_as_uint(a);
}

__global__ void __launch_bounds__(256, 4)
nmu_kernel(const float* __restrict__ x, const float* __restrict__ M,
           float* __restrict__ out) {
    __shared__ float us[NMU_R * NMU_D];            // 8 KB  (x - 1)
    __shared__ float pw[NMU_NW * NMU_R * NMU_O];   // 8 KB  partials

    const int tid  = threadIdx.x;
    const int warp = tid >> 5;
    const int o    = tid & 31;
    const int b0   = blockIdx.x * NMU_R;
    const int d0   = warp * NMU_DPW;

    // --- weights: 16 packed m-pairs into registers (coalesced, L1/L2-hot) ---
    unsigned long long m2[16];
    {
        const float* __restrict__ Mg = M + (size_t)d0 * NMU_O + o;
        #pragma unroll
        for (int k = 0; k < 16; k++) {
            float a = __saturatef(__ldg(Mg + (2 * k + 0) * NMU_O));
            float b = __saturatef(__ldg(Mg + (2 * k + 1) * NMU_O));
            m2[k] = pack2(a, b);
        }
    }

    // --- stage u = x - 1 (coalesced float4, subtract folded into copy) ---
    {
        const float4* __restrict__ xg = (const float4*)(x + (size_t)b0 * NMU_D);
        float4* us4 = (float4*)us;
        #pragma unroll
        for (int i = 0; i < (NMU_R * NMU_D / 4) / 256; i++) {   // 2 iters
            float4 v = xg[tid + i * 256];
            v.x -= 1.0f; v.y -= 1.0f; v.z -= 1.0f; v.w -= 1.0f;
            us4[tid + i * 256] = v;
        }
    }
    __syncthreads();

    // --- hot loop: 8 rows; per row two 16-d half-chunks ---
    const unsigned long long ONE2 = 0x3f8000003f800000ULL;
    #pragma unroll 2
    for (int r = 0; r < NMU_R; r++) {
        const ulonglong2* __restrict__ ur =
            (const ulonglong2*)(us + r * NMU_D + d0);

        unsigned long long p, q, t;
        // half-chunk 0: d0 .. d0+15
        {
            ulonglong2 v0 = ur[0], v1 = ur[1], v2 = ur[2], v3 = ur[3];
            t = f2_fma(m2[0], v0.x, ONE2);  p = t;
            t = f2_fma(m2[1], v0.y, ONE2);  q = t;
            t = f2_fma(m2[2], v1.x, ONE2);  p = f2_mul(p, t);
            t = f2_fma(m2[3], v1.y, ONE2);  q = f2_mul(q, t);
            t = f2_fma(m2[4], v2.x, ONE2);  p = f2_mul(p, t);
            t = f2_fma(m2[5], v2.y, ONE2);  q = f2_mul(q, t);
            t = f2_fma(m2[6], v3.x, ONE2);  p = f2_mul(p, t);
            t = f2_fma(m2[7], v3.y, ONE2);  q = f2_mul(q, t);
        }
        // half-chunk 1: d0+16 .. d0+31
        {
            ulonglong2 v4 = ur[4], v5 = ur[5], v6 = ur[6], v7 = ur[7];
            t = f2_fma(m2[ 8], v4.x, ONE2);  p = f2_mul(p, t);
            t = f2_fma(m2[ 9], v4.y, ONE2);  q = f2_mul(q, t);
            t = f2_fma(m2[10], v5.x, ONE2);  p = f2_mul(p, t);
            t = f2_fma(m2[11], v5.y, ONE2);  q = f2_mul(q, t);
            t = f2_fma(m2[12], v6.x, ONE2);  p = f2_mul(p, t);
            t = f2_fma(m2[13], v6.y, ONE2);  q = f2_mul(q, t);
            t = f2_fma(m2[14], v7.x, ONE2);  p = f2_mul(p, t);
            t = f2_fma(m2[15], v7.y, ONE2);  q = f2_mul(q, t);
        }

        unsigned long long pr = f2_mul(p, q);
        float lo = __uint_as_float((unsigned)(pr & 0xffffffffULL));
        float hi = __uint_as_float((unsigned)(pr >> 32));
        pw[(warp * NMU_R + r) * NMU_O + o] = lo * hi;   // conflict-free STS.32
    }
    __syncthreads();

    // --- combine 8 warp-partials; exactly 1 output per thread ---
    {
        const int row = tid >> 5;          // 0..7
        const int oo  = tid & 31;
        const float* pp = pw + row * NMU_O + oo;
        const int S = NMU_R * NMU_O;       // 256 floats between warp slabs
        float a0 = pp[0 * S] * pp[1 * S];
        float a1 = pp[2 * S] * pp[3 * S];
        float a2 = pp[4 * S] * pp[5 * S];
        float a3 = pp[6 * S] * pp[7 * S];
        out[(size_t)(b0 + row) * NMU_O + oo] = (a0 * a1) * (a2 * a3);
    }
}

extern "C" void kernel_launch(void* const* d_in, const int* in_sizes, int n_in,
                              void* d_out, int out_size) {
    const float* x = (const float*)d_in[0];   // [16384, 256]
    const float* M = (const float*)d_in[1];   // [256, 32]
    float* out = (float*)d_out;               // [16384, 32]

    const int B = in_sizes[0] / NMU_D;        // 16384

    nmu_kernel<<<B / NMU_R, 256>>>(x, M, out);
}